// round 8
// baseline (speedup 1.0000x reference)
#include <cuda_runtime.h>
#include <cstdint>

#define Bsz 128
#define Hdim 256
#define Wdim 1024
#define N_HOLES 5
#define PROB 1.0f
#define HOLE_MINW (Wdim / 10)              // 102
#define HOLE_MINH (Hdim / 10)              // 25
#define N_TOTAL ((long long)Bsz * Hdim * Wdim)   // 33,554,432 floats

#define GRID 1024                          // <= resident slots @ occ 8
#define NT 256
#define TOTT ((long long)GRID * NT)        // 262,144 threads = 2 images (f2)
#define JB 8                               // batched loads per iteration
#define KITER 8                            // 64 total accesses per thread
#define IMG_F2 (Hdim * Wdim / 2)           // 131,072 float2 per image
#define NHOLE_T (Bsz * N_HOLES)            // 640

__device__ float g_partials[GRID];
__device__ float g_mean;
__device__ int   g_count = 0;              // last block resets -> replay-safe
__device__ int   g_epoch = 0;              // monotonic: bumps once per launch

// Fused kernel:
//  setup:   all 640 hole rects -> smem (reused by fill phase)
//  phase 1: strided copy+reduce; per-warp 64-bit mask skips stores whose
//           64-float chunk is fully inside an active hole (warp-uniform,
//           full-line skips -- fill overwrites those chunks later)
//  sync:    ticket counter; last block -> g_mean, bumps epoch
//  phase 2: blocks 0..639 fill their hole rect with g_mean
__global__ void __launch_bounds__(NT, 8) fused_cutout_kernel(
    const float2* __restrict__ x, float2* __restrict__ out,
    const int* __restrict__ xs, const int* __restrict__ ys,
    const int* __restrict__ xs_w_raw, const int* __restrict__ ys_h_raw,
    const float* __restrict__ act_rand)
{
    const int epoch0 = *(volatile int*)&g_epoch;

    // ---- setup: hole rect table (x0, x1, y0, y1); inactive -> sentinel ----
    __shared__ int4 srect[NHOLE_T];        // 10 KB
    for (int t = threadIdx.x; t < NHOLE_T; t += NT) {
        const int hw_ = xs_w_raw[t] + HOLE_MINW;
        const int hh_ = ys_h_raw[t] + HOLE_MINH;
        const int cx = xs[t], cy = ys[t];
        int4 r;
        r.x = min(max(cx - hw_ / 2, 0), Wdim - 2);
        r.y = min(max(cx + hw_ / 2, 1), Wdim - 1);
        r.z = min(max(cy - hh_ / 2, 0), Hdim - 2);
        r.w = min(max(cy + hh_ / 2, 1), Hdim - 1);
        if (!(act_rand[t] < PROB)) r.x = 1 << 30;   // never contains
        srect[t] = r;
    }
    __syncthreads();

    // ---- per-warp geometry: (h, w-chunk) fixed across all 64 accesses ----
    const long long tg = (long long)blockIdx.x * NT + threadIdx.x;
    const int lane = threadIdx.x & 31;
    const int par = (tg >= IMG_F2) ? 1 : 0;          // image parity
    const int f   = (int)(tg & (IMG_F2 - 1));        // within-image f2 idx
    const int h   = f >> 9;                          // 512 f2 per row
    const int wlo = ((f & 511) & ~31) * 2;           // warp's 64-float chunk
    const int whi = wlo + 63;

    // 64-bit skip mask: bit m -> image b = 2m + par fully covers this chunk
    uint64_t skipmask;
    {
        bool s0 = false, s1 = false;
        const int b0i = (2 * lane + par) * N_HOLES;
        const int b1i = (2 * (lane + 32) + par) * N_HOLES;
        #pragma unroll
        for (int n = 0; n < N_HOLES; ++n) {
            int4 r0 = srect[b0i + n];
            s0 |= (h >= r0.z) & (h <= r0.w) & (wlo >= r0.x) & (whi <= r0.y);
            int4 r1 = srect[b1i + n];
            s1 |= (h >= r1.z) & (h <= r1.w) & (wlo >= r1.x) & (whi <= r1.y);
        }
        uint32_t mlo = __ballot_sync(0xFFFFFFFFu, s0);
        uint32_t mhi = __ballot_sync(0xFFFFFFFFu, s1);
        skipmask = (uint64_t)mlo | ((uint64_t)mhi << 32);
    }

    // ---- phase 1: copy + reduce, 8 loads in flight, masked stores ----
    float s = 0.0f;
    #pragma unroll 1
    for (int k = 0; k < KITER; ++k) {
        const long long b0 = (long long)k * (JB * TOTT) + tg;
        float2 v[JB];
        #pragma unroll
        for (int j = 0; j < JB; ++j)
            v[j] = x[b0 + (long long)j * TOTT];
        #pragma unroll
        for (int j = 0; j < JB; ++j) {
            s += v[j].x + v[j].y;
            const int m = k * JB + j;
            if (!((skipmask >> m) & 1ull))
                out[b0 + (long long)j * TOTT] = v[j];
        }
    }

    #pragma unroll
    for (int o = 16; o > 0; o >>= 1)
        s += __shfl_down_sync(0xFFFFFFFFu, s, o);
    __shared__ float ws[8];
    const int warp = threadIdx.x >> 5;
    if (lane == 0) ws[warp] = s;
    __syncthreads();
    __shared__ int is_last;
    if (threadIdx.x == 0) {
        float v = ws[0];
        #pragma unroll
        for (int k = 1; k < 8; ++k) v += ws[k];
        g_partials[blockIdx.x] = v;
        __threadfence();
        int ticket = atomicAdd(&g_count, 1);
        is_last = (ticket == GRID - 1);
    }
    __syncthreads();

    if (is_last) {
        float s2 = 0.0f;
        for (int k = threadIdx.x; k < GRID; k += NT)
            s2 += g_partials[k];
        #pragma unroll
        for (int o = 16; o > 0; o >>= 1)
            s2 += __shfl_down_sync(0xFFFFFFFFu, s2, o);
        __shared__ float wf[8];
        if (lane == 0) wf[warp] = s2;
        __syncthreads();
        if (threadIdx.x == 0) {
            float t = wf[0];
            #pragma unroll
            for (int k = 1; k < 8; ++k) t += wf[k];
            g_mean = t * (1.0f / (float)N_TOTAL);
            g_count = 0;
            __threadfence();
            *(volatile int*)&g_epoch = epoch0 + 1;   // release
        }
    }

    // ---- phase 2 only for blocks owning a hole ----
    const int hole = blockIdx.x;
    if (hole >= NHOLE_T) return;
    const int4 r = srect[hole];
    if (r.x >= Wdim) return;               // inactive sentinel

    if (threadIdx.x == 0) {
        while (*(volatile int*)&g_epoch == epoch0)
            __nanosleep(64);
    }
    __syncthreads();
    __threadfence();                       // acquire
    const float fill = *(volatile float*)&g_mean;
    const float4 f4 = make_float4(fill, fill, fill, fill);

    const int b = hole / N_HOLES;
    const int x0 = r.x, x1 = r.y, y0 = r.z, y1 = r.w;
    const int a0 = (x0 + 3) & ~3;          // first aligned float index
    const int a1 = (x1 + 1) & ~3;          // exclusive aligned end
    const int nvec = (a1 - a0) >> 2;

    const int qx = threadIdx.x & 63;
    const int ry = threadIdx.x >> 6;

    const int wl = x0 + qx;
    const bool do_l = (qx < 3) && (wl < a0);
    const int wr = a1 + (qx - 3);
    const bool do_r = (qx >= 3) && (qx < 6) && (wr <= x1);

    float* const base = (float*)out + (size_t)b * Hdim * Wdim + a0;
    for (int hh = y0 + ry; hh <= y1; hh += 4) {
        float* const row = base + (size_t)hh * Wdim;
        if (do_l) row[wl - a0] = fill;
        if (do_r) row[wr - a0] = fill;
        float4* const rowv = reinterpret_cast<float4*>(row);
        for (int q = qx; q < nvec; q += 64)
            rowv[q] = f4;
    }
}

extern "C" void kernel_launch(void* const* d_in, const int* in_sizes, int n_in,
                              void* d_out, int out_size) {
    const float* x        = (const float*)d_in[0];
    const int*   xs       = (const int*)d_in[1];
    const int*   ys       = (const int*)d_in[2];
    const int*   xs_w_raw = (const int*)d_in[3];
    const int*   ys_h_raw = (const int*)d_in[4];
    const float* act_rand = (const float*)d_in[5];
    float* out = (float*)d_out;

    fused_cutout_kernel<<<GRID, NT>>>((const float2*)x, (float2*)out,
                                      xs, ys, xs_w_raw, ys_h_raw, act_rand);
}